// round 17
// baseline (speedup 1.0000x reference)
#include <cuda_runtime.h>
#include <cstdint>

// Masked LeNet-C3 conv via TF32 mma.sync.m16n8k8 implicit GEMM on sm_103.
// x: [64,6,512,512] f32, W: [16,6,5,5] f32, b: [16] f32 -> out: [64,16,508,508] f32
//
// Round 17 = Round 16 main loop (proven, 1326us) +
//  (a) fully-unrolled input loader (45 LDGs in flight -> load phase ~1k cyc, was ~4-9k)
//  (b) 4 y-sub-tiles per CTA: B-table/bias built once, grid 16384 -> 4096.

#define NIC 6
#define NOC 16
#define IH 512
#define IW 512
#define OH 508
#define OW 508
#define TILE_W 64
#define TILE_H 16
#define SUBS 4              // y sub-tiles per CTA (64 output rows)
#define IN_ROWS 20          // TILE_H + 4
#define IN_W 72             // 64 + 4 halo + 4 zero pad (A reads reach col 70)
#define IC_STRIDE (IN_ROWS * IN_W)
#define NTHREADS 256
#define SMEM_BYTES ((NIC * IC_STRIDE) * 4 + (NIC * 5 * NOC * 8) * 4 + NOC * 4)

__host__ __device__ constexpr float conn(int ic, int oc) {
    constexpr int M[NIC][NOC] = {
        {1,0,0,0,1,1,1,0,0,1,1,1,1,0,1,1},
        {1,1,0,0,0,1,1,1,0,0,1,1,1,1,0,1},
        {1,1,1,0,0,0,1,1,1,0,0,1,0,1,1,1},
        {0,1,1,1,0,0,1,1,1,1,0,0,1,0,1,1},
        {0,0,1,1,1,0,0,1,1,1,1,0,1,1,0,1},
        {0,0,0,1,1,1,0,0,1,1,1,1,0,1,1,1},
    };
    return (float)M[ic][oc];
}

__device__ __forceinline__ uint32_t cvt_tf32(float f) {
    uint32_t r;
    asm("cvt.rna.tf32.f32 %0, %1;" : "=r"(r) : "f"(f));
    return r;
}

#define MMA_TF32(d0, d1, d2, d3, a0, a1, a2, a3, b0, b1) \
    asm("mma.sync.aligned.m16n8k8.row.col.f32.tf32.tf32.f32 " \
        "{%0,%1,%2,%3}, {%4,%5,%6,%7}, {%8,%9}, {%0,%1,%2,%3};" \
        : "+f"(d0), "+f"(d1), "+f"(d2), "+f"(d3) \
        : "r"(a0), "r"(a1), "r"(a2), "r"(a3), "r"(b0), "r"(b1))

__global__ __launch_bounds__(NTHREADS, 2)
void conv_c3_mma(const float* __restrict__ x,
                 const float* __restrict__ W,
                 const float* __restrict__ b,
                 float* __restrict__ out)
{
    extern __shared__ float smem[];
    float*    s_in = smem;                                    // 6*20*72 floats
    uint32_t* s_B  = (uint32_t*)(smem + NIC * IC_STRIDE);     // 6*5*16*8 u32
    float*    s_b  = (float*)(s_B + NIC * 5 * NOC * 8);

    const int tid  = threadIdx.x;
    const int lane = tid & 31;
    const int warp = tid >> 5;
    const int n    = blockIdx.z;
    const int byT  = blockIdx.y * (SUBS * TILE_H);   // CTA covers 64 output rows
    const int bx0  = blockIdx.x * TILE_W;

    // ---- Masked weight table (once per CTA): s_B[((ic*5+ky)*16+oc)*8+kx] ----
    #pragma unroll
    for (int idx = tid; idx < NIC * 5 * NOC * 8; idx += NTHREADS) {
        int kx   = idx & 7;
        int oc   = (idx >> 3) & 15;
        int rest = idx >> 7;
        int ic   = rest / 5;
        int ky   = rest - ic * 5;
        float wv = 0.0f;
        if (kx < 5) wv = W[oc * (NIC * 25) + ic * 25 + ky * 5 + kx] * conn(ic, oc);
        s_B[idx] = cvt_tf32(wv);
    }
    if (tid < NOC) s_b[tid] = b[tid];

    const float* xin = x + (size_t)n * NIC * IH * IW;

    const int g    = lane >> 2;
    const int c4   = lane & 3;
    const int aoff = g + c4;
    const int boff = g * 8 + c4;
    const int r0   = 2 * warp;
    const int xg   = bx0 + g;
    const float* rpw = s_in + r0 * IN_W + aoff;

    #pragma unroll 1
    for (int sub = 0; sub < SUBS; sub++) {
        const int by0 = byT + sub * TILE_H;
        __syncthreads();   // previous compute done before overwriting s_in

        // ---- Input tile loader: warp per (ic,row), FULLY UNROLLED for MLP ----
        #pragma unroll
        for (int rowi = warp; rowi < NIC * IN_ROWS; rowi += NTHREADS / 32) {
            int ic = rowi / IN_ROWS;
            int r  = rowi - ic * IN_ROWS;
            int gy = by0 + r;
            const float* src = xin + ((size_t)ic * IH + gy) * IW + bx0;
            float* dst = s_in + (ic * IN_ROWS + r) * IN_W;
            #pragma unroll
            for (int cc = 0; cc < 3; cc++) {
                int c = lane + cc * 32;
                if (c < IN_W) {
                    float v = 0.0f;
                    if (c < TILE_W + 4 && gy < IH && bx0 + c < IW) v = __ldg(src + c);
                    dst[c] = __uint_as_float(cvt_tf32(v));
                }
            }
        }
        __syncthreads();

        // ---- Main loop: 2 rows/warp, ky-rolled A buffers (identical to R16) ----
#define DECL_MT(r, mt) \
        float ar##r##_##mt##_0_0 = 0.f, ar##r##_##mt##_0_1 = 0.f, \
              ar##r##_##mt##_0_2 = 0.f, ar##r##_##mt##_0_3 = 0.f, \
              ar##r##_##mt##_1_0 = 0.f, ar##r##_##mt##_1_1 = 0.f, \
              ar##r##_##mt##_1_2 = 0.f, ar##r##_##mt##_1_3 = 0.f;
        DECL_MT(0,0) DECL_MT(0,1) DECL_MT(0,2) DECL_MT(0,3)
        DECL_MT(1,0) DECL_MT(1,1) DECL_MT(1,2) DECL_MT(1,3)

#define DECL_AB(P) \
        uint32_t P##_0_0, P##_0_1, P##_0_2, P##_0_3, \
                 P##_1_0, P##_1_1, P##_1_2, P##_1_3, \
                 P##_2_0, P##_2_1, P##_2_2, P##_2_3, \
                 P##_3_0, P##_3_1, P##_3_2, P##_3_3;
        DECL_AB(X) DECL_AB(Y)

#define LOAD_A(P, rpp) { \
        P##_0_0 = __float_as_uint((rpp)[0]);  P##_0_1 = __float_as_uint((rpp)[8]); \
        P##_0_2 = __float_as_uint((rpp)[4]);  P##_0_3 = __float_as_uint((rpp)[12]); \
        P##_1_0 = __float_as_uint((rpp)[16]); P##_1_1 = __float_as_uint((rpp)[24]); \
        P##_1_2 = __float_as_uint((rpp)[20]); P##_1_3 = __float_as_uint((rpp)[28]); \
        P##_2_0 = __float_as_uint((rpp)[32]); P##_2_1 = __float_as_uint((rpp)[40]); \
        P##_2_2 = __float_as_uint((rpp)[36]); P##_2_3 = __float_as_uint((rpp)[44]); \
        P##_3_0 = __float_as_uint((rpp)[48]); P##_3_1 = __float_as_uint((rpp)[56]); \
        P##_3_2 = __float_as_uint((rpp)[52]); P##_3_3 = __float_as_uint((rpp)[60]); }

#define LOADB(ky) { \
        const uint32_t* Bq = Bp + (ky) * (NOC * 8); \
        bL0 = Bq[boff];      bL1 = Bq[boff + 4]; \
        bH0 = Bq[64 + boff]; bH1 = Bq[64 + boff + 4]; }

#define MMA_MT_R(r, mt, P) \
        MMA_TF32(ar##r##_##mt##_0_0, ar##r##_##mt##_0_1, ar##r##_##mt##_0_2, ar##r##_##mt##_0_3, \
                 P##_##mt##_0, P##_##mt##_1, P##_##mt##_2, P##_##mt##_3, bL0, bL1); \
        MMA_TF32(ar##r##_##mt##_1_0, ar##r##_##mt##_1_1, ar##r##_##mt##_1_2, ar##r##_##mt##_1_3, \
                 P##_##mt##_0, P##_##mt##_1, P##_##mt##_2, P##_##mt##_3, bH0, bH1);

#define MMA_ROW(r, P) \
        MMA_MT_R(r, 0, P) MMA_MT_R(r, 1, P) MMA_MT_R(r, 2, P) MMA_MT_R(r, 3, P)

        #pragma unroll 1
        for (int ic = 0; ic < NIC; ic++) {
            const float*    rp = rpw + ic * IC_STRIDE;
            const uint32_t* Bp = s_B + ic * 5 * (NOC * 8);
            uint32_t bL0, bL1, bH0, bH1;

            LOAD_A(X, rp)                 // smem row r0
            LOAD_A(Y, rp + IN_W)          // smem row r0+1
            LOADB(0)  MMA_ROW(0, X)  MMA_ROW(1, Y)
            LOAD_A(X, rp + 2 * IN_W)      // smem row r0+2
            LOADB(1)  MMA_ROW(0, Y)  MMA_ROW(1, X)
            LOAD_A(Y, rp + 3 * IN_W)      // smem row r0+3
            LOADB(2)  MMA_ROW(0, X)  MMA_ROW(1, Y)
            LOAD_A(X, rp + 4 * IN_W)      // smem row r0+4
            LOADB(3)  MMA_ROW(0, Y)  MMA_ROW(1, X)
            LOAD_A(Y, rp + 5 * IN_W)      // smem row r0+5
            LOADB(4)  MMA_ROW(0, X)  MMA_ROW(1, Y)
        }

        // ---- Epilogue ----
#define STORE_MT_R(r, mt, h) { \
        int oc0 = h * 8 + 2 * c4; \
        float bo0 = s_b[oc0], bo1 = s_b[oc0 + 1]; \
        float* o0 = orow + (size_t)oc0 * OH * OW; \
        float* o1 = o0 + (size_t)OH * OW; \
        int x0 = xg + mt * 16; \
        if (x0 < OW) { \
            o0[x0] = ar##r##_##mt##_##h##_0 + bo0; \
            o1[x0] = ar##r##_##mt##_##h##_1 + bo1; \
        } \
        if (x0 + 8 < OW) { \
            o0[x0 + 8] = ar##r##_##mt##_##h##_2 + bo0; \
            o1[x0 + 8] = ar##r##_##mt##_##h##_3 + bo1; \
        } }

        {
            const int y = by0 + r0;
            if (y < OH) {
                float* orow = out + ((size_t)n * NOC * OH + y) * OW;
                STORE_MT_R(0, 0, 0) STORE_MT_R(0, 0, 1)
                STORE_MT_R(0, 1, 0) STORE_MT_R(0, 1, 1)
                STORE_MT_R(0, 2, 0) STORE_MT_R(0, 2, 1)
                STORE_MT_R(0, 3, 0) STORE_MT_R(0, 3, 1)
            }
        }
        {
            const int y = by0 + r0 + 1;
            if (y < OH) {
                float* orow = out + ((size_t)n * NOC * OH + y) * OW;
                STORE_MT_R(1, 0, 0) STORE_MT_R(1, 0, 1)
                STORE_MT_R(1, 1, 0) STORE_MT_R(1, 1, 1)
                STORE_MT_R(1, 2, 0) STORE_MT_R(1, 2, 1)
                STORE_MT_R(1, 3, 0) STORE_MT_R(1, 3, 1)
            }
        }
    }
}

extern "C" void kernel_launch(void* const* d_in, const int* in_sizes, int n_in,
                              void* d_out, int out_size) {
    const float* x = (const float*)d_in[0];
    const float* W = (const float*)d_in[1];
    const float* b = (const float*)d_in[2];
    float* out = (float*)d_out;

    cudaFuncSetAttribute(conv_c3_mma,
                         cudaFuncAttributeMaxDynamicSharedMemorySize, SMEM_BYTES);

    const int n_batch = in_sizes[0] / (NIC * IH * IW);   // 64
    dim3 grid((OW + TILE_W - 1) / TILE_W,                       // 8
              (OH + SUBS * TILE_H - 1) / (SUBS * TILE_H),       // 8
              n_batch);                                          // 64
    conv_c3_mma<<<grid, NTHREADS, SMEM_BYTES>>>(x, W, b, out);
}